// round 14
// baseline (speedup 1.0000x reference)
#include <cuda_runtime.h>
#include <cuda_bf16.h>
#include <cuda_fp16.h>
#include <math.h>
#include <stdint.h>

#define B_    2
#define S_    2048
#define HID_  1024
#define H_    16
#define DK_   64
#define HDK_  1024
#define M_    4096
#define SCALE_ 0.125f
#define LOG2E_ 1.4426950408889634f
#define NEG_  -1000000000.0f

// Scratch (allocation-free device globals)
__device__ __half g_q16[B_*H_*S_*DK_];                   // Q fp16 (scaled by SCALE*log2e)
__device__ __half g_k16[B_*H_*S_*DK_];                   // K fp16
__device__ __half g_v16[B_*H_*S_*DK_];                   // V fp16
__device__ __half g_xhh[M_*HDK_], g_xhl[M_*HDK_];        // attn out fp16 hi/lo
__device__ float g_maskf[B_*S_];                         // mask as float 0/1
__device__ __half g_w16[4u*HID_*HDK_];                   // W fp16 single, [g][k][n]
__device__ __half g_insh[3u*M_*HID_], g_insl[3u*M_*HID_]; // q/k/v inputs fp16 hi/lo

// ---------------------------------------------------------------------------
// sm_80-class PTX helpers (harness targets compute_103: no 'a' features)
// ---------------------------------------------------------------------------
__device__ __forceinline__ uint32_t smem_u32(const void* p) {
    uint32_t a;
    asm("{ .reg .u64 t; cvta.to.shared.u64 t, %1; cvt.u32.u64 %0, t; }"
        : "=r"(a) : "l"(p));
    return a;
}
__device__ __forceinline__ void lds4(uint32_t* r, uint32_t addr) {
    asm volatile("ldmatrix.sync.aligned.m8n8.x4.shared.b16 {%0,%1,%2,%3}, [%4];"
                 : "=r"(r[0]), "=r"(r[1]), "=r"(r[2]), "=r"(r[3]) : "r"(addr));
}
__device__ __forceinline__ void lds4t(uint32_t* r, uint32_t addr) {
    asm volatile("ldmatrix.sync.aligned.m8n8.x4.trans.shared.b16 {%0,%1,%2,%3}, [%4];"
                 : "=r"(r[0]), "=r"(r[1]), "=r"(r[2]), "=r"(r[3]) : "r"(addr));
}
// fp16 MMA (everything)
__device__ __forceinline__ void mma16816h(float* d, const uint32_t* a, const uint32_t* b) {
    asm volatile(
        "mma.sync.aligned.m16n8k16.row.col.f32.f16.f16.f32 "
        "{%0,%1,%2,%3}, {%4,%5,%6,%7}, {%8,%9}, {%0,%1,%2,%3};"
        : "+f"(d[0]), "+f"(d[1]), "+f"(d[2]), "+f"(d[3])
        : "r"(a[0]), "r"(a[1]), "r"(a[2]), "r"(a[3]), "r"(b[0]), "r"(b[1]));
}
#define CP_ASYNC16(dst, src) \
    asm volatile("cp.async.cg.shared.global [%0], [%1], 16;" :: "r"(dst), "l"(src))
#define CP_COMMIT() asm volatile("cp.async.commit_group;" ::: "memory")
#define CP_WAIT0()  asm volatile("cp.async.wait_group 0;" ::: "memory")
#define CP_WAIT1()  asm volatile("cp.async.wait_group 1;" ::: "memory")

__device__ __forceinline__ void split2h(float a, float b, uint32_t& hi, uint32_t& lo) {
    __half ah = __float2half_rn(a);
    __half bh = __float2half_rn(b);
    __half al = __float2half_rn(a - __half2float(ah));
    __half bl = __float2half_rn(b - __half2float(bh));
    hi = (uint32_t)__half_as_ushort(ah) | ((uint32_t)__half_as_ushort(bh) << 16);
    lo = (uint32_t)__half_as_ushort(al) | ((uint32_t)__half_as_ushort(bl) << 16);
}
__device__ __forceinline__ uint32_t pack_h2(float a, float b) {
    __half2 h = __floats2half2_rn(a, b);
    return *(uint32_t*)&h;
}

// FMA-pipe exp2 (base-2 domain input), degree-4, rel err ~4e-5.
__device__ __forceinline__ float exp2_fast(float z0) {
    float z = fmaxf(z0, -126.0f);
    float r = z + 12582912.0f;
    int   n = __float_as_int(r) - 0x4B400000;
    float f = z - (r - 12582912.0f);
    float gg = f * 0.6931471805599453f;
    float p = fmaf(gg, 0.041666667f, 0.166666667f);
    p = fmaf(gg, p, 0.5f);
    p = fmaf(gg, p, 1.0f);
    p = fmaf(gg, p, 1.0f);
    return __int_as_float((n + 127) << 23) * p;
}

// ---------------------------------------------------------------------------
// Prep: g 0-3 = W fp32->fp16; g 4-6 = inputs fp32->fp16 hi/lo; g 7 = mask
// ---------------------------------------------------------------------------
__global__ __launch_bounds__(256) void prep_kernel(
    const float* __restrict__ q, const float* __restrict__ k, const float* __restrict__ v,
    const float* __restrict__ Wq, const float* __restrict__ Wk,
    const float* __restrict__ Wv, const float* __restrict__ Wo,
    const int* __restrict__ mask)
{
    const int g = blockIdx.y;
    const int idx = blockIdx.x * 256 + threadIdx.x;
    if (g == 7) {
        if (idx < B_ * S_) g_maskf[idx] = (mask[idx] != 0) ? 1.0f : 0.0f;
        return;
    }
    if (g < 4) {
        if (idx >= HID_ * HDK_ / 4) return;
        const float* src = (g == 0) ? Wq : (g == 1) ? Wk : (g == 2) ? Wv : Wo;
        float4 x = ((const float4*)src)[idx];
        uint2* D = (uint2*)(g_w16 + (size_t)g * HID_ * HDK_);
        D[idx] = make_uint2(pack_h2(x.x, x.y), pack_h2(x.z, x.w));
    } else {
        const float* src = (g == 4) ? q : (g == 5) ? k : v;
        float4 x = ((const float4*)src)[idx];
        uint32_t h0, l0, h1, l1;
        split2h(x.x, x.y, h0, l0);
        split2h(x.z, x.w, h1, l1);
        uint2* DH = (uint2*)(g_insh + (size_t)(g - 4) * M_ * HID_);
        uint2* DL = (uint2*)(g_insl + (size_t)(g - 4) * M_ * HID_);
        DH[idx] = make_uint2(h0, h1);
        DL[idx] = make_uint2(l0, l1);
    }
}

// ---------------------------------------------------------------------------
// fp16x2 HMMA GEMM core (R13): X = fp16 hi/lo, W = fp16 single. Full cp.async,
// K-chunk 32, 3-stage pipeline. CTA 128x128, 8 warps, 2 CTAs/SM.
// ---------------------------------------------------------------------------
#define A_PAD 40
#define OFF_AL 10240
#define OFF_BH 20480
#define STAGE_ 29184
#define GSM_BYTES (3 * STAGE_)

__device__ __forceinline__ void cpA(uint32_t abase,
                                    const __half* __restrict__ XH,
                                    const __half* __restrict__ XL,
                                    int m0, int k0, int tid) {
    #pragma unroll
    for (int i = 0; i < 4; i++) {
        const int idx = tid + i * 256;
        const int mat = idx >> 9, rem = idx & 511;
        const int row = rem >> 2, c8 = (rem & 3) * 8;
        const size_t g = (size_t)(m0 + row) * HID_ + k0 + c8;
        const uint32_t d = abase + mat * OFF_AL + (uint32_t)(row * A_PAD + c8) * 2;
        CP_ASYNC16(d, (mat == 0 ? XH : XL) + g);
    }
}
__device__ __forceinline__ void cpB(uint32_t bbase,
                                    const __half* __restrict__ Wp,
                                    int n0, int k0, int tid) {
    #pragma unroll
    for (int i = 0; i < 2; i++) {
        const int idx = tid + i * 256;
        const int row = idx >> 4, c8 = (idx & 15) * 8;
        const size_t g = (size_t)(k0 + row) * HDK_ + n0 + c8;
        const uint32_t d = bbase + (uint32_t)(row * 136 + c8) * 2;
        CP_ASYNC16(d, Wp + g);
    }
}

__device__ __forceinline__ void gemm_main(
    const __half* __restrict__ XH, const __half* __restrict__ XL,
    const __half* __restrict__ W,
    int m0, int n0, uint32_t smb, float acc[2][8][4])
{
    const int tid  = threadIdx.x;
    const int lane = tid & 31;
    const int warp = tid >> 5;
    const int m0w  = (warp >> 1) * 32;
    const int n0w  = (warp & 1) * 64;
    const int arow = m0w + (lane & 15);
    const int acol = (lane >> 4) * 8;
    const int brow = lane & 15;
    const int bcol = n0w + (lane >> 4) * 8;

    #pragma unroll
    for (int pc = 0; pc < 2; ++pc) {
        cpA(smb + pc * STAGE_, XH, XL, m0, pc * 32, tid);
        cpB(smb + pc * STAGE_ + OFF_BH, W, n0, pc * 32, tid);
        CP_COMMIT();
    }

    int sidx = 0;
    for (int c = 0; c < 32; ++c) {
        if (c < 31) { CP_WAIT1(); } else { CP_WAIT0(); }
        __syncthreads();
        const uint32_t sb = smb + (uint32_t)sidx * STAGE_;

        if (c + 2 < 32) {
            const int pidx = (sidx + 2 >= 3) ? sidx - 1 : sidx + 2;
            const uint32_t nb = smb + (uint32_t)pidx * STAGE_;
            cpA(nb, XH, XL, m0, (c + 2) * 32, tid);
            cpB(nb + OFF_BH, W, n0, (c + 2) * 32, tid);
            CP_COMMIT();
        }
        sidx = (sidx + 1 >= 3) ? 0 : sidx + 1;

        #pragma unroll
        for (int ks = 0; ks < 2; ++ks) {
            uint32_t ah[2][4], al[2][4];
            #pragma unroll
            for (int mf = 0; mf < 2; ++mf) {
                const uint32_t aoff =
                    (uint32_t)((arow + mf * 16) * A_PAD + ks * 16 + acol) * 2;
                lds4(ah[mf], sb + aoff);
                lds4(al[mf], sb + OFF_AL + aoff);
            }
            #pragma unroll
            for (int np = 0; np < 4; ++np) {
                const uint32_t boff =
                    (uint32_t)((ks * 16 + brow) * 136 + bcol + np * 16) * 2;
                uint32_t bh[4];
                lds4t(bh, sb + OFF_BH + boff);
                #pragma unroll
                for (int mf = 0; mf < 2; ++mf) {
                    mma16816h(acc[mf][2*np],   ah[mf], bh);
                    mma16816h(acc[mf][2*np+1], ah[mf], bh + 2);
                    mma16816h(acc[mf][2*np],   al[mf], bh);
                    mma16816h(acc[mf][2*np+1], al[mf], bh + 2);
                }
            }
        }
    }
}

// ---------------------------------------------------------------------------
// Projection GEMMs -> head-major fp16 (Q pre-scaled by SCALE*log2e)
// ---------------------------------------------------------------------------
__global__ __launch_bounds__(256, 2) void proj_tc_kernel(
    const float* __restrict__ bq, const float* __restrict__ bk, const float* __restrict__ bv)
{
    extern __shared__ char smc[];
    const uint32_t smb = smem_u32(smc);

    const int z = blockIdx.z;
    const float* bias = (z == 0) ? bq : (z == 1) ? bk : bv;
    const __half* XH = g_insh + (size_t)z * M_ * HID_;
    const __half* XL = g_insl + (size_t)z * M_ * HID_;
    const __half* W  = g_w16 + (size_t)z * HID_ * HDK_;
    __half* Y = (z == 0) ? g_q16 : (z == 1) ? g_k16 : g_v16;
    const float osc = (z == 0) ? SCALE_ * LOG2E_ : 1.0f;

    const int m0 = blockIdx.y * 128, n0 = blockIdx.x * 128;
    float acc[2][8][4] = {};
    gemm_main(XH, XL, W, m0, n0, smb, acc);

    const int lane = threadIdx.x & 31, warp = threadIdx.x >> 5;
    const int m0w = (warp >> 1) * 32, n0w = (warp & 1) * 64;
    #pragma unroll
    for (int mf = 0; mf < 2; ++mf) {
        #pragma unroll
        for (int nf = 0; nf < 8; ++nf) {
            const int mr = m0 + m0w + mf * 16 + (lane >> 2);
            const int nn = n0 + n0w + nf * 8 + (lane & 3) * 2;
            const int hh = nn >> 6, dk = nn & 63;
            const float b0 = bias[nn], b1 = bias[nn + 1];
            #pragma unroll
            for (int rr = 0; rr < 2; ++rr) {
                const int m = mr + rr * 8;
                const int bb = m >> 11, ss = m & 2047;
                float v0 = (acc[mf][nf][2*rr]     + b0) * osc;
                float v1 = (acc[mf][nf][2*rr + 1] + b1) * osc;
                size_t idx = (((size_t)bb * H_ + hh) * S_ + ss) * DK_ + dk;
                *(uint32_t*)&Y[idx] = pack_h2(v0, v1);
            }
        }
    }
}

// ---------------------------------------------------------------------------
// fp16 HMMA flash attention. CTA = 128 q-rows, 256 threads (8 warps),
// 2 CTAs/SM. Per-warp work identical to R13 (16 q-rows x 64 keys/tile).
// 2-stage unified ring: {KH 9216 | VH 9216 | BIAS 128x272B 34816} = 53248.
// ---------------------------------------------------------------------------
#define BIAS_OFF 18432
#define BIAS_ROW 272
#define ATT_ST   53248
#define ATTN_SMEM (2 * ATT_ST)    // 106496
#define ONES2 0x3C003C00u

__device__ __forceinline__ void cp_tile(uint32_t dstbase,
    const __half* __restrict__ K16, const __half* __restrict__ V16,
    const float* __restrict__ biasq,      // attn_bias + ((b*H+h)*S + q0)*S
    int k0, int tid)
{
    // K/V: 1024 chunks (2 mats x 512), 256 threads x 4
    #pragma unroll
    for (int i = 0; i < 4; i++) {
        int idx = tid + i * 256;
        int mat = idx >> 9, rem = idx & 511;
        int row = rem >> 3, c8 = (rem & 7) * 8;
        const __half* src = ((mat == 0) ? K16 : V16) + (size_t)(k0 + row) * DK_ + c8;
        uint32_t dst = dstbase + mat * 9216 + (uint32_t)(row * 72 + c8) * 2;
        CP_ASYNC16(dst, src);
    }
    // bias: 128 rows x 64 floats = 2048 chunks, 256 threads x 8
    #pragma unroll
    for (int i = 0; i < 8; i++) {
        int idx = tid + i * 256;
        int row = idx >> 4, c4 = (idx & 15) * 4;
        const float* src = biasq + (size_t)row * S_ + k0 + c4;
        uint32_t dst = dstbase + BIAS_OFF + (uint32_t)(row * BIAS_ROW + c4 * 4);
        CP_ASYNC16(dst, src);
    }
}

__global__ __launch_bounds__(256, 2) void attn_tc_kernel(
    const float* __restrict__ attn_bias, const int* __restrict__ mask)
{
    extern __shared__ char sm[];
    const uint32_t smb = smem_u32(sm);
    const int tid = threadIdx.x;
    const int lane = tid & 31, warp = tid >> 5;
    const int g = lane >> 2, tig = lane & 3;
    const int q0 = blockIdx.x * 128;
    const int h = blockIdx.y, b = blockIdx.z;

    const size_t hb = ((size_t)b * H_ + h) * S_ * DK_;
    const __half* Qg  = g_q16 + hb + (size_t)q0 * DK_;
    const __half* K16 = g_k16 + hb;
    const __half* V16 = g_v16 + hb;
    const float* biasq = attn_bias + (((size_t)b * H_ + h) * S_ + q0) * S_;

    // Q fragments -> registers (mma A-frag layout), loaded once
    uint32_t qh[4][4];
    {
        const int r0 = warp * 16 + g;
        #pragma unroll
        for (int ks = 0; ks < 4; ks++) {
            const int c = ks * 16 + tig * 2;
            qh[ks][0] = *(const uint32_t*)&Qg[(size_t)r0 * DK_ + c];
            qh[ks][1] = *(const uint32_t*)&Qg[(size_t)(r0 + 8) * DK_ + c];
            qh[ks][2] = *(const uint32_t*)&Qg[(size_t)r0 * DK_ + c + 8];
            qh[ks][3] = *(const uint32_t*)&Qg[(size_t)(r0 + 8) * DK_ + c + 8];
        }
    }

    // Prologue: tile 0 -> stage 0
    cp_tile(smb, K16, V16, biasq, 0, tid);
    CP_COMMIT();

    const int qr0 = q0 + warp * 16 + g;
    const float* mfb = g_maskf + b * S_;

    float oa[8][4] = {};
    float lacc[4] = {};
    const uint32_t bones[2] = {ONES2, ONES2};

    const uint32_t kbase = (uint32_t)(((lane & 7) + ((lane & 16) >> 1)) * 72
                                      + (lane & 8)) * 2;
    const uint32_t vbase = (uint32_t)((lane & 15) * 72 + (lane >> 4) * 8) * 2;
    const char* bsm0 = sm + BIAS_OFF + (warp * 16 + g) * BIAS_ROW + tig * 8;

    for (int t = 0; t < 32; ++t) {
        const int k0 = t * 64;
        const int s = t & 1;
        const uint32_t sb = smb + (uint32_t)s * ATT_ST;
        const char* bsm = bsm0 + s * ATT_ST;

        if (t + 1 < 32) {
            cp_tile(smb + (uint32_t)(s ^ 1) * ATT_ST, K16, V16, biasq, (t + 1) * 64, tid);
            CP_COMMIT();
        }

        if (t + 1 < 32) { CP_WAIT1(); } else { CP_WAIT0(); }
        __syncthreads();

        // S*log2e = Q K^T (Q pre-scaled by SCALE*log2e)
        float sa[8][4];
        #pragma unroll
        for (int i = 0; i < 8; i++)
            #pragma unroll
            for (int j = 0; j < 4; j++) sa[i][j] = 0.f;

        #pragma unroll
        for (int ks = 0; ks < 4; ks++) {
            #pragma unroll
            for (int nf = 0; nf < 4; nf++) {
                uint32_t kaddr = sb + kbase + (uint32_t)(nf * 16 * 72 + ks * 16) * 2;
                uint32_t kh4[4];
                lds4(kh4, kaddr);
                mma16816h(sa[2*nf],   qh[ks], kh4);
                mma16816h(sa[2*nf+1], qh[ks], kh4 + 2);
            }
        }

        // p = 2^(mask-sel(s*log2e) + b*log2e); bias from smem (prefetched)
        #pragma unroll
        for (int nf = 0; nf < 8; nf++) {
            float2 b0 = *(const float2*)(bsm + nf * 32);
            float2 b1 = *(const float2*)(bsm + 8 * BIAS_ROW + nf * 32);
            float2 mm = *(const float2*)&mfb[k0 + 8 * nf + 2 * tig];
            sa[nf][0] = exp2_fast(fmaf(b0.x, LOG2E_, (mm.x != 0.f) ? sa[nf][0] : NEG_));
            sa[nf][1] = exp2_fast(fmaf(b0.y, LOG2E_, (mm.y != 0.f) ? sa[nf][1] : NEG_));
            sa[nf][2] = exp2_fast(fmaf(b1.x, LOG2E_, (mm.x != 0.f) ? sa[nf][2] : NEG_));
            sa[nf][3] = exp2_fast(fmaf(b1.y, LOG2E_, (mm.y != 0.f) ? sa[nf][3] : NEG_));
        }

        // O += P V; lsum += P @ ones (P single fp16, V single fp16)
        #pragma unroll
        for (int ks2 = 0; ks2 < 4; ks2++) {
            uint32_t ph[4];
            ph[0] = pack_h2(sa[2*ks2][0],   sa[2*ks2][1]);
            ph[1] = pack_h2(sa[2*ks2][2],   sa[2*ks2][3]);
            ph[2] = pack_h2(sa[2*ks2+1][0], sa[2*ks2+1][1]);
            ph[3] = pack_h2(sa[2*ks2+1][2], sa[2*ks2+1][3]);
            mma16816h(lacc, ph, bones);
            #pragma unroll
            for (int nf4 = 0; nf4 < 4; nf4++) {
                uint32_t vaddr = sb + 9216 + vbase
                               + (uint32_t)(ks2 * 16 * 72 + nf4 * 16) * 2;
                uint32_t vh4[4];
                lds4t(vh4, vaddr);
                mma16816h(oa[2*nf4],   ph, vh4);
                mma16816h(oa[2*nf4+1], ph, vh4 + 2);
            }
        }
        __syncthreads();   // all warps done with stage s before t+1's cp refills it
    }

    // epilogue: normalize by MMA row sums, q-mask, write fp16 hi/lo xh
    float qm0 = (mask[b * S_ + qr0]     != 0) ? 1.f : 0.f;
    float qm8 = (mask[b * S_ + qr0 + 8] != 0) ? 1.f : 0.f;
    float inv0 = qm0 / lacc[0], inv8 = qm8 / lacc[2];
    #pragma unroll
    for (int nf = 0; nf < 8; nf++) {
        int col = h * DK_ + 8 * nf + 2 * tig;
        uint32_t hi, lo;
        split2h(oa[nf][0] * inv0, oa[nf][1] * inv0, hi, lo);
        size_t i0 = (size_t)(b * S_ + qr0) * HDK_ + col;
        *(uint32_t*)&g_xhh[i0] = hi;
        *(uint32_t*)&g_xhl[i0] = lo;
        split2h(oa[nf][2] * inv8, oa[nf][3] * inv8, hi, lo);
        size_t i8 = (size_t)(b * S_ + qr0 + 8) * HDK_ + col;
        *(uint32_t*)&g_xhh[i8] = hi;
        *(uint32_t*)&g_xhl[i8] = lo;
    }
}

// ---------------------------------------------------------------------------
// Output GEMM: out = xh @ Wo + bo
// ---------------------------------------------------------------------------
__global__ __launch_bounds__(256, 2) void out_tc_kernel(
    const float* __restrict__ bo, float* __restrict__ out)
{
    extern __shared__ char smc[];
    const uint32_t smb = smem_u32(smc);

    const __half* W = g_w16 + (size_t)3 * HID_ * HDK_;

    const int m0 = blockIdx.y * 128, n0 = blockIdx.x * 128;
    float acc[2][8][4] = {};
    gemm_main(g_xhh, g_xhl, W, m0, n0, smb, acc);

    const int lane = threadIdx.x & 31, warp = threadIdx.x >> 5;
    const int m0w = (warp >> 1) * 32, n0w = (warp & 1) * 64;
    #pragma unroll
    for (int mf = 0; mf < 2; ++mf) {
        #pragma unroll
        for (int nf = 0; nf < 8; ++nf) {
            const int mr = m0 + m0w + mf * 16 + (lane >> 2);
            const int nn = n0 + n0w + nf * 8 + (lane & 3) * 2;
            const float b0 = bo[nn], b1 = bo[nn + 1];
            *(float2*)&out[(size_t)mr * HDK_ + nn] =
                make_float2(acc[mf][nf][0] + b0, acc[mf][nf][1] + b1);
            *(float2*)&out[(size_t)(mr + 8) * HDK_ + nn] =
                make_float2(acc[mf][nf][2] + b0, acc[mf][nf][3] + b1);
        }
    }
}

// ---------------------------------------------------------------------------
extern "C" void kernel_launch(void* const* d_in, const int* in_sizes, int n_in,
                              void* d_out, int out_size)
{
    const float* q         = (const float*)d_in[0];
    const float* k         = (const float*)d_in[1];
    const float* v         = (const float*)d_in[2];
    const float* attn_bias = (const float*)d_in[3];
    const int*   mask      = (const int*)  d_in[4];
    const float* Wq        = (const float*)d_in[5];
    const float* bq        = (const float*)d_in[6];
    const float* Wk        = (const float*)d_in[7];
    const float* bk        = (const float*)d_in[8];
    const float* Wv        = (const float*)d_in[9];
    const float* bv        = (const float*)d_in[10];
    const float* Wo        = (const float*)d_in[11];
    const float* bo        = (const float*)d_in[12];
    float* out = (float*)d_out;

    static int configured = 0;
    if (!configured) {
        cudaFuncSetAttribute(proj_tc_kernel, cudaFuncAttributeMaxDynamicSharedMemorySize, GSM_BYTES);
        cudaFuncSetAttribute(out_tc_kernel,  cudaFuncAttributeMaxDynamicSharedMemorySize, GSM_BYTES);
        cudaFuncSetAttribute(attn_tc_kernel, cudaFuncAttributeMaxDynamicSharedMemorySize, ATTN_SMEM);
        configured = 1;
    }

    prep_kernel<<<dim3(M_ * HID_ / 4 / 256, 8), 256>>>(q, k, v, Wq, Wk, Wv, Wo, mask);

    proj_tc_kernel<<<dim3(HDK_ / 128, M_ / 128, 3), 256, GSM_BYTES>>>(bq, bk, bv);

    attn_tc_kernel<<<dim3(S_ / 128, H_, B_), 256, ATTN_SMEM>>>(attn_bias, mask);

    out_tc_kernel<<<dim3(HDK_ / 128, M_ / 128), 256, GSM_BYTES>>>(bo, out);
}

// round 16
// speedup vs baseline: 1.0040x; 1.0040x over previous
#include <cuda_runtime.h>
#include <cuda_bf16.h>
#include <cuda_fp16.h>
#include <math.h>
#include <stdint.h>

#define B_    2
#define S_    2048
#define HID_  1024
#define H_    16
#define DK_   64
#define HDK_  1024
#define M_    4096
#define SCALE_ 0.125f
#define LOG2E_ 1.4426950408889634f
#define NEG_  -1000000000.0f

// Scratch (allocation-free device globals)
__device__ __half g_q16[B_*H_*S_*DK_];                   // Q fp16 (scaled by SCALE*log2e)
__device__ __half g_k16[B_*H_*S_*DK_];                   // K fp16
__device__ __half g_v16[B_*H_*S_*DK_];                   // V fp16
__device__ __half g_xhh[M_*HDK_], g_xhl[M_*HDK_];        // attn out fp16 hi/lo
__device__ float g_maskf[B_*S_];                         // mask as float 0/1
__device__ __half g_w16[4u*HID_*HDK_];                   // W fp16 single, [g][k][n]
__device__ __half g_insh[3u*M_*HID_], g_insl[3u*M_*HID_]; // q/k/v inputs fp16 hi/lo

// ---------------------------------------------------------------------------
// sm_80-class PTX helpers (harness targets compute_103: no 'a' features)
// ---------------------------------------------------------------------------
__device__ __forceinline__ uint32_t smem_u32(const void* p) {
    uint32_t a;
    asm("{ .reg .u64 t; cvta.to.shared.u64 t, %1; cvt.u32.u64 %0, t; }"
        : "=r"(a) : "l"(p));
    return a;
}
__device__ __forceinline__ void lds4(uint32_t* r, uint32_t addr) {
    asm volatile("ldmatrix.sync.aligned.m8n8.x4.shared.b16 {%0,%1,%2,%3}, [%4];"
                 : "=r"(r[0]), "=r"(r[1]), "=r"(r[2]), "=r"(r[3]) : "r"(addr));
}
__device__ __forceinline__ void lds4t(uint32_t* r, uint32_t addr) {
    asm volatile("ldmatrix.sync.aligned.m8n8.x4.trans.shared.b16 {%0,%1,%2,%3}, [%4];"
                 : "=r"(r[0]), "=r"(r[1]), "=r"(r[2]), "=r"(r[3]) : "r"(addr));
}
// fp16 MMA (everything)
__device__ __forceinline__ void mma16816h(float* d, const uint32_t* a, const uint32_t* b) {
    asm volatile(
        "mma.sync.aligned.m16n8k16.row.col.f32.f16.f16.f32 "
        "{%0,%1,%2,%3}, {%4,%5,%6,%7}, {%8,%9}, {%0,%1,%2,%3};"
        : "+f"(d[0]), "+f"(d[1]), "+f"(d[2]), "+f"(d[3])
        : "r"(a[0]), "r"(a[1]), "r"(a[2]), "r"(a[3]), "r"(b[0]), "r"(b[1]));
}
#define CP_ASYNC16(dst, src) \
    asm volatile("cp.async.cg.shared.global [%0], [%1], 16;" :: "r"(dst), "l"(src))
#define CP_COMMIT() asm volatile("cp.async.commit_group;" ::: "memory")
#define CP_WAIT0()  asm volatile("cp.async.wait_group 0;" ::: "memory")
#define CP_WAIT1()  asm volatile("cp.async.wait_group 1;" ::: "memory")

__device__ __forceinline__ void split2h(float a, float b, uint32_t& hi, uint32_t& lo) {
    __half ah = __float2half_rn(a);
    __half bh = __float2half_rn(b);
    __half al = __float2half_rn(a - __half2float(ah));
    __half bl = __float2half_rn(b - __half2float(bh));
    hi = (uint32_t)__half_as_ushort(ah) | ((uint32_t)__half_as_ushort(bh) << 16);
    lo = (uint32_t)__half_as_ushort(al) | ((uint32_t)__half_as_ushort(bl) << 16);
}
__device__ __forceinline__ uint32_t pack_h2(float a, float b) {
    __half2 h = __floats2half2_rn(a, b);
    return *(uint32_t*)&h;
}

// FMA-pipe exp2 (base-2 domain input), degree-4, rel err ~4e-5.
__device__ __forceinline__ float exp2_fast(float z0) {
    float z = fmaxf(z0, -126.0f);
    float r = z + 12582912.0f;
    int   n = __float_as_int(r) - 0x4B400000;
    float f = z - (r - 12582912.0f);
    float gg = f * 0.6931471805599453f;
    float p = fmaf(gg, 0.041666667f, 0.166666667f);
    p = fmaf(gg, p, 0.5f);
    p = fmaf(gg, p, 1.0f);
    p = fmaf(gg, p, 1.0f);
    return __int_as_float((n + 127) << 23) * p;
}

// ---------------------------------------------------------------------------
// Prep: g 0-3 = W fp32->fp16; g 4-6 = inputs fp32->fp16 hi/lo; g 7 = mask
// ---------------------------------------------------------------------------
__global__ __launch_bounds__(256) void prep_kernel(
    const float* __restrict__ q, const float* __restrict__ k, const float* __restrict__ v,
    const float* __restrict__ Wq, const float* __restrict__ Wk,
    const float* __restrict__ Wv, const float* __restrict__ Wo,
    const int* __restrict__ mask)
{
    const int g = blockIdx.y;
    const int idx = blockIdx.x * 256 + threadIdx.x;
    if (g == 7) {
        if (idx < B_ * S_) g_maskf[idx] = (mask[idx] != 0) ? 1.0f : 0.0f;
        return;
    }
    if (g < 4) {
        if (idx >= HID_ * HDK_ / 4) return;
        const float* src = (g == 0) ? Wq : (g == 1) ? Wk : (g == 2) ? Wv : Wo;
        float4 x = ((const float4*)src)[idx];
        uint2* D = (uint2*)(g_w16 + (size_t)g * HID_ * HDK_);
        D[idx] = make_uint2(pack_h2(x.x, x.y), pack_h2(x.z, x.w));
    } else {
        const float* src = (g == 4) ? q : (g == 5) ? k : v;
        float4 x = ((const float4*)src)[idx];
        uint32_t h0, l0, h1, l1;
        split2h(x.x, x.y, h0, l0);
        split2h(x.z, x.w, h1, l1);
        uint2* DH = (uint2*)(g_insh + (size_t)(g - 4) * M_ * HID_);
        uint2* DL = (uint2*)(g_insl + (size_t)(g - 4) * M_ * HID_);
        DH[idx] = make_uint2(h0, h1);
        DL[idx] = make_uint2(l0, l1);
    }
}

// ---------------------------------------------------------------------------
// fp16x2 HMMA GEMM core (R13 proven): X = fp16 hi/lo, W = fp16 single.
// K-chunk 32, 3-stage pipeline (prefetch distance 2). CTA 128x128, 8 warps,
// 2 CTAs/SM. Stage: AH[128][40] 10240 | AL 10240 | BH[32][136] 8704 = 29184.
// (A row stride 80 B and B row stride 272 B are 16B-aligned for cp.async.)
// ---------------------------------------------------------------------------
#define A_PAD 40
#define OFF_AL 10240
#define OFF_BH 20480
#define STAGE_ 29184
#define GSM_BYTES (3 * STAGE_)

__device__ __forceinline__ void cpA(uint32_t abase,
                                    const __half* __restrict__ XH,
                                    const __half* __restrict__ XL,
                                    int m0, int k0, int tid) {
    #pragma unroll
    for (int i = 0; i < 4; i++) {
        const int idx = tid + i * 256;           // 1024 chunks (2 mats x 512)
        const int mat = idx >> 9, rem = idx & 511;
        const int row = rem >> 2, c8 = (rem & 3) * 8;
        const size_t g = (size_t)(m0 + row) * HID_ + k0 + c8;
        const uint32_t d = abase + mat * OFF_AL + (uint32_t)(row * A_PAD + c8) * 2;
        CP_ASYNC16(d, (mat == 0 ? XH : XL) + g);
    }
}
__device__ __forceinline__ void cpB(uint32_t bbase,
                                    const __half* __restrict__ Wp,
                                    int n0, int k0, int tid) {
    #pragma unroll
    for (int i = 0; i < 2; i++) {
        const int idx = tid + i * 256;           // 512 chunks (32 rows x 16)
        const int row = idx >> 4, c8 = (idx & 15) * 8;
        const size_t g = (size_t)(k0 + row) * HDK_ + n0 + c8;
        const uint32_t d = bbase + (uint32_t)(row * 136 + c8) * 2;
        CP_ASYNC16(d, Wp + g);
    }
}

__device__ __forceinline__ void gemm_main(
    const __half* __restrict__ XH, const __half* __restrict__ XL,
    const __half* __restrict__ W,
    int m0, int n0, uint32_t smb, float acc[2][8][4])
{
    const int tid  = threadIdx.x;
    const int lane = tid & 31;
    const int warp = tid >> 5;
    const int m0w  = (warp >> 1) * 32;
    const int n0w  = (warp & 1) * 64;
    const int arow = m0w + (lane & 15);
    const int acol = (lane >> 4) * 8;
    const int brow = lane & 15;
    const int bcol = n0w + (lane >> 4) * 8;

    // Prologue: chunks 0,1 -> stages 0,1
    #pragma unroll
    for (int pc = 0; pc < 2; ++pc) {
        cpA(smb + pc * STAGE_, XH, XL, m0, pc * 32, tid);
        cpB(smb + pc * STAGE_ + OFF_BH, W, n0, pc * 32, tid);
        CP_COMMIT();
    }

    int sidx = 0;
    for (int c = 0; c < 32; ++c) {
        if (c < 31) { CP_WAIT1(); } else { CP_WAIT0(); }
        __syncthreads();
        const uint32_t sb = smb + (uint32_t)sidx * STAGE_;

        if (c + 2 < 32) {
            const int pidx = (sidx + 2 >= 3) ? sidx - 1 : sidx + 2;
            const uint32_t nb = smb + (uint32_t)pidx * STAGE_;
            cpA(nb, XH, XL, m0, (c + 2) * 32, tid);
            cpB(nb + OFF_BH, W, n0, (c + 2) * 32, tid);
            CP_COMMIT();
        }
        sidx = (sidx + 1 >= 3) ? 0 : sidx + 1;

        #pragma unroll
        for (int ks = 0; ks < 2; ++ks) {
            uint32_t ah[2][4], al[2][4];
            #pragma unroll
            for (int mf = 0; mf < 2; ++mf) {
                const uint32_t aoff =
                    (uint32_t)((arow + mf * 16) * A_PAD + ks * 16 + acol) * 2;
                lds4(ah[mf], sb + aoff);
                lds4(al[mf], sb + OFF_AL + aoff);
            }
            #pragma unroll
            for (int np = 0; np < 4; ++np) {
                const uint32_t boff =
                    (uint32_t)((ks * 16 + brow) * 136 + bcol + np * 16) * 2;
                uint32_t bh[4];
                lds4t(bh, sb + OFF_BH + boff);
                #pragma unroll
                for (int mf = 0; mf < 2; ++mf) {
                    mma16816h(acc[mf][2*np],   ah[mf], bh);
                    mma16816h(acc[mf][2*np+1], ah[mf], bh + 2);
                    mma16816h(acc[mf][2*np],   al[mf], bh);
                    mma16816h(acc[mf][2*np+1], al[mf], bh + 2);
                }
            }
        }
    }
}

// ---------------------------------------------------------------------------
// Projection GEMMs -> head-major fp16 (Q pre-scaled by SCALE*log2e)
// ---------------------------------------------------------------------------
__global__ __launch_bounds__(256, 2) void proj_tc_kernel(
    const float* __restrict__ bq, const float* __restrict__ bk, const float* __restrict__ bv)
{
    extern __shared__ char smc[];
    const uint32_t smb = smem_u32(smc);

    const int z = blockIdx.z;
    const float* bias = (z == 0) ? bq : (z == 1) ? bk : bv;
    const __half* XH = g_insh + (size_t)z * M_ * HID_;
    const __half* XL = g_insl + (size_t)z * M_ * HID_;
    const __half* W  = g_w16 + (size_t)z * HID_ * HDK_;
    __half* Y = (z == 0) ? g_q16 : (z == 1) ? g_k16 : g_v16;
    const float osc = (z == 0) ? SCALE_ * LOG2E_ : 1.0f;

    const int m0 = blockIdx.y * 128, n0 = blockIdx.x * 128;
    float acc[2][8][4] = {};
    gemm_main(XH, XL, W, m0, n0, smb, acc);

    const int lane = threadIdx.x & 31, warp = threadIdx.x >> 5;
    const int m0w = (warp >> 1) * 32, n0w = (warp & 1) * 64;
    #pragma unroll
    for (int mf = 0; mf < 2; ++mf) {
        #pragma unroll
        for (int nf = 0; nf < 8; ++nf) {
            const int mr = m0 + m0w + mf * 16 + (lane >> 2);
            const int nn = n0 + n0w + nf * 8 + (lane & 3) * 2;
            const int hh = nn >> 6, dk = nn & 63;
            const float b0 = bias[nn], b1 = bias[nn + 1];
            #pragma unroll
            for (int rr = 0; rr < 2; ++rr) {
                const int m = mr + rr * 8;
                const int bb = m >> 11, ss = m & 2047;
                float v0 = (acc[mf][nf][2*rr]     + b0) * osc;
                float v1 = (acc[mf][nf][2*rr + 1] + b1) * osc;
                size_t idx = (((size_t)bb * H_ + hh) * S_ + ss) * DK_ + dk;
                *(uint32_t*)&Y[idx] = pack_h2(v0, v1);
            }
        }
    }
}

// ---------------------------------------------------------------------------
// fp16 HMMA flash attention (R13 exact: best measured attention config).
// Fixed-ref softmax, base-2 poly exp, ones-MMA row sums.
// CTA = 64 q-rows, 128 threads (4 warps), 3 CTAs/SM.
// 2-stage unified ring: {KH 9216 | VH 9216 | BIAS 64x272B 17408} = 35840/stage.
// ---------------------------------------------------------------------------
#define BIAS_OFF 18432
#define BIAS_ROW 272
#define ATT_ST   35840
#define ATTN_SMEM (2 * ATT_ST)
#define ONES2 0x3C003C00u

__device__ __forceinline__ void cp_tile(uint32_t dstbase,
    const __half* __restrict__ K16, const __half* __restrict__ V16,
    const float* __restrict__ biasq,      // attn_bias + ((b*H+h)*S + q0)*S
    int k0, int tid)
{
    // K/V: 1024 chunks (2 mats x 512)
    #pragma unroll
    for (int i = 0; i < 8; i++) {
        int idx = tid + i * 128;
        int mat = idx >> 9, rem = idx & 511;
        int row = rem >> 3, c8 = (rem & 7) * 8;
        const __half* src = ((mat == 0) ? K16 : V16) + (size_t)(k0 + row) * DK_ + c8;
        uint32_t dst = dstbase + mat * 9216 + (uint32_t)(row * 72 + c8) * 2;
        CP_ASYNC16(dst, src);
    }
    // bias: 64 rows x 64 floats = 1024 chunks
    #pragma unroll
    for (int i = 0; i < 8; i++) {
        int idx = tid + i * 128;
        int row = idx >> 4, c4 = (idx & 15) * 4;
        const float* src = biasq + (size_t)row * S_ + k0 + c4;
        uint32_t dst = dstbase + BIAS_OFF + (uint32_t)(row * BIAS_ROW + c4 * 4);
        CP_ASYNC16(dst, src);
    }
}

__global__ __launch_bounds__(128, 3) void attn_tc_kernel(
    const float* __restrict__ attn_bias, const int* __restrict__ mask)
{
    extern __shared__ char sm[];
    const uint32_t smb = smem_u32(sm);
    const int tid = threadIdx.x;
    const int lane = tid & 31, warp = tid >> 5;
    const int g = lane >> 2, tig = lane & 3;
    const int q0 = blockIdx.x * 64;
    const int h = blockIdx.y, b = blockIdx.z;

    const size_t hb = ((size_t)b * H_ + h) * S_ * DK_;
    const __half* Qg  = g_q16 + hb + (size_t)q0 * DK_;
    const __half* K16 = g_k16 + hb;
    const __half* V16 = g_v16 + hb;
    const float* biasq = attn_bias + (((size_t)b * H_ + h) * S_ + q0) * S_;

    // Q fragments -> registers (mma A-frag layout), loaded once
    uint32_t qh[4][4];
    {
        const int r0 = warp * 16 + g;
        #pragma unroll
        for (int ks = 0; ks < 4; ks++) {
            const int c = ks * 16 + tig * 2;
            qh[ks][0] = *(const uint32_t*)&Qg[(size_t)r0 * DK_ + c];
            qh[ks][1] = *(const uint32_t*)&Qg[(size_t)(r0 + 8) * DK_ + c];
            qh[ks][2] = *(const uint32_t*)&Qg[(size_t)r0 * DK_ + c + 8];
            qh[ks][3] = *(const uint32_t*)&Qg[(size_t)(r0 + 8) * DK_ + c + 8];
        }
    }

    // Prologue: tile 0 -> stage 0
    cp_tile(smb, K16, V16, biasq, 0, tid);
    CP_COMMIT();

    const int qr0 = q0 + warp * 16 + g;
    const float* mfb = g_maskf + b * S_;

    float oa[8][4] = {};
    float lacc[4] = {};
    const uint32_t bones[2] = {ONES2, ONES2};

    const uint32_t kbase = (uint32_t)(((lane & 7) + ((lane & 16) >> 1)) * 72
                                      + (lane & 8)) * 2;
    const uint32_t vbase = (uint32_t)((lane & 15) * 72 + (lane >> 4) * 8) * 2;
    const char* bsm0 = sm + BIAS_OFF + (warp * 16 + g) * BIAS_ROW + tig * 8;

    for (int t = 0; t < 32; ++t) {
        const int k0 = t * 64;
        const int s = t & 1;
        const uint32_t sb = smb + (uint32_t)s * ATT_ST;
        const char* bsm = bsm0 + s * ATT_ST;

        if (t + 1 < 32) {
            cp_tile(smb + (uint32_t)(s ^ 1) * ATT_ST, K16, V16, biasq, (t + 1) * 64, tid);
            CP_COMMIT();
        }

        if (t + 1 < 32) { CP_WAIT1(); } else { CP_WAIT0(); }
        __syncthreads();

        // S*log2e = Q K^T (Q pre-scaled by SCALE*log2e)
        float sa[8][4];
        #pragma unroll
        for (int i = 0; i < 8; i++)
            #pragma unroll
            for (int j = 0; j < 4; j++) sa[i][j] = 0.f;

        #pragma unroll
        for (int ks = 0; ks < 4; ks++) {
            #pragma unroll
            for (int nf = 0; nf < 4; nf++) {
                uint32_t kaddr = sb + kbase + (uint32_t)(nf * 16 * 72 + ks * 16) * 2;
                uint32_t kh4[4];
                lds4(kh4, kaddr);
                mma16816h(sa[2*nf],   qh[ks], kh4);
                mma16816h(sa[2*nf+1], qh[ks], kh4 + 2);
            }
        }

        // p = 2^(mask-sel(s*log2e) + b*log2e); bias from smem (prefetched)
        #pragma unroll
        for (int nf = 0; nf < 8; nf++) {
            float2 b0 = *(const float2*)(bsm + nf * 32);
            float2 b1 = *(const float2*)(bsm + 8 * BIAS_ROW + nf * 32);
            float2 mm = *(const float2*)&mfb[k0 + 8 * nf + 2 * tig];
            sa[nf][0] = exp2_fast(fmaf(b0.x, LOG2E_, (mm.x != 0.f) ? sa[nf][0] : NEG_));
            sa[nf][1] = exp2_fast(fmaf(b0.y, LOG2E_, (mm.y != 0.f) ? sa[nf][1] : NEG_));
            sa[nf][2] = exp2_fast(fmaf(b1.x, LOG2E_, (mm.x != 0.f) ? sa[nf][2] : NEG_));
            sa[nf][3] = exp2_fast(fmaf(b1.y, LOG2E_, (mm.y != 0.f) ? sa[nf][3] : NEG_));
        }

        // O += P V; lsum += P @ ones (P single fp16, V single fp16)
        #pragma unroll
        for (int ks2 = 0; ks2 < 4; ks2++) {
            uint32_t ph[4];
            ph[0] = pack_h2(sa[2*ks2][0],   sa[2*ks2][1]);
            ph[1] = pack_h2(sa[2*ks2][2],   sa[2*ks2][3]);
            ph[2] = pack_h2(sa[2*ks2+1][0], sa[2*ks2+1][1]);
            ph[3] = pack_h2(sa[2*ks2+1][2], sa[2*ks2+1][3]);
            mma16816h(lacc, ph, bones);
            #pragma unroll
            for (int nf4 = 0; nf4 < 4; nf4++) {
                uint32_t vaddr = sb + 9216 + vbase
                               + (uint32_t)(ks2 * 16 * 72 + nf4 * 16) * 2;
                uint32_t vh4[4];
                lds4t(vh4, vaddr);
                mma16816h(oa[2*nf4],   ph, vh4);
                mma16816h(oa[2*nf4+1], ph, vh4 + 2);
            }
        }
        __syncthreads();   // all warps done with stage s before t+1's cp refills it
    }

    // epilogue: normalize by MMA row sums, q-mask, write fp16 hi/lo xh
    float qm0 = (mask[b * S_ + qr0]     != 0) ? 1.f : 0.f;
    float qm8 = (mask[b * S_ + qr0 + 8] != 0) ? 1.f : 0.f;
    float inv0 = qm0 / lacc[0], inv8 = qm8 / lacc[2];
    #pragma unroll
    for (int nf = 0; nf < 8; nf++) {
        int col = h * DK_ + 8 * nf + 2 * tig;
        uint32_t hi, lo;
        split2h(oa[nf][0] * inv0, oa[nf][1] * inv0, hi, lo);
        size_t i0 = (size_t)(b * S_ + qr0) * HDK_ + col;
        *(uint32_t*)&g_xhh[i0] = hi;
        *(uint32_t*)&g_xhl[i0] = lo;
        split2h(oa[nf][2] * inv8, oa[nf][3] * inv8, hi, lo);
        size_t i8 = (size_t)(b * S_ + qr0 + 8) * HDK_ + col;
        *(uint32_t*)&g_xhh[i8] = hi;
        *(uint32_t*)&g_xhl[i8] = lo;
    }
}

// ---------------------------------------------------------------------------
// Output GEMM: out = xh @ Wo + bo
// ---------------------------------------------------------------------------
__global__ __launch_bounds__(256, 2) void out_tc_kernel(
    const float* __restrict__ bo, float* __restrict__ out)
{
    extern __shared__ char smc[];
    const uint32_t smb = smem_u32(smc);

    const __half* W = g_w16 + (size_t)3 * HID_ * HDK_;

    const int m0 = blockIdx.y * 128, n0 = blockIdx.x * 128;
    float acc[2][8][4] = {};
    gemm_main(g_xhh, g_xhl, W, m0, n0, smb, acc);

    const int lane = threadIdx.x & 31, warp = threadIdx.x >> 5;
    const int m0w = (warp >> 1) * 32, n0w = (warp & 1) * 64;
    #pragma unroll
    for (int mf = 0; mf < 2; ++mf) {
        #pragma unroll
        for (int nf = 0; nf < 8; ++nf) {
            const int mr = m0 + m0w + mf * 16 + (lane >> 2);
            const int nn = n0 + n0w + nf * 8 + (lane & 3) * 2;
            const float b0 = bo[nn], b1 = bo[nn + 1];
            *(float2*)&out[(size_t)mr * HDK_ + nn] =
                make_float2(acc[mf][nf][0] + b0, acc[mf][nf][1] + b1);
            *(float2*)&out[(size_t)(mr + 8) * HDK_ + nn] =
                make_float2(acc[mf][nf][2] + b0, acc[mf][nf][3] + b1);
        }
    }
}

// ---------------------------------------------------------------------------
extern "C" void kernel_launch(void* const* d_in, const int* in_sizes, int n_in,
                              void* d_out, int out_size)
{
    const float* q         = (const float*)d_in[0];
    const float* k         = (const float*)d_in[1];
    const float* v         = (const float*)d_in[2];
    const float* attn_bias = (const float*)d_in[3];
    const int*   mask      = (const int*)  d_in[4];
    const float* Wq        = (const float*)d_in[5];
    const float* bq        = (const float*)d_in[6];
    const float* Wk        = (const float*)d_in[7];
    const float* bk        = (const float*)d_in[8];
    const float* Wv        = (const float*)d_in[9];
    const float* bv        = (const float*)d_in[10];
    const float* Wo        = (const float*)d_in[11];
    const float* bo        = (const float*)d_in[12];
    float* out = (float*)d_out;

    static int configured = 0;
    if (!configured) {
        cudaFuncSetAttribute(proj_tc_kernel, cudaFuncAttributeMaxDynamicSharedMemorySize, GSM_BYTES);
        cudaFuncSetAttribute(out_tc_kernel,  cudaFuncAttributeMaxDynamicSharedMemorySize, GSM_BYTES);
        cudaFuncSetAttribute(attn_tc_kernel, cudaFuncAttributeMaxDynamicSharedMemorySize, ATTN_SMEM);
        configured = 1;
    }

    prep_kernel<<<dim3(M_ * HID_ / 4 / 256, 8), 256>>>(q, k, v, Wq, Wk, Wv, Wo, mask);

    proj_tc_kernel<<<dim3(HDK_ / 128, M_ / 128, 3), 256, GSM_BYTES>>>(bq, bk, bv);

    attn_tc_kernel<<<dim3(S_ / 64, H_, B_), 128, ATTN_SMEM>>>(attn_bias, mask);

    out_tc_kernel<<<dim3(HDK_ / 128, M_ / 128), 256, GSM_BYTES>>>(bo, out);
}